// round 6
// baseline (speedup 1.0000x reference)
#include <cuda_runtime.h>

#define X 256
#define Y 256
#define Z 192
#define YX (X*Y)
#define NB 2
#define TX 128         // output tile width (elements)
#define TY 16          // output tile height
#define CW 34          // float4 columns = (TX+8)/4
#define CH 20          // rows = TY+4 (halo 2 each side)
#define NTH (CW*CH)    // 680 threads
#define ZCHUNKS 4
#define ZCK (Z/ZCHUNKS) /* 48 */

__device__ __forceinline__ float4 fmin4(float4 a, float4 b) {
    return make_float4(fminf(a.x,b.x), fminf(a.y,b.y), fminf(a.z,b.z), fminf(a.w,b.w));
}
__device__ __forceinline__ float4 fmax4(float4 a, float4 b) {
    return make_float4(fmaxf(a.x,b.x), fmaxf(a.y,b.y), fmaxf(a.z,b.z), fmaxf(a.w,b.w));
}
__device__ __forceinline__ float min3(float a, float b, float c) { return fminf(a, fminf(b, c)); }
__device__ __forceinline__ float max3(float a, float b, float c) { return fmaxf(a, fmaxf(b, c)); }

// out = relu(img - dilate3x3x3(erode3x3x3(img))), stride 1, pad 1.
// erode = min-pool (pad +inf), dilate = max-pool (pad -inf via domain mask).
// Identical dataflow to the 90.6us float2 kernel, but each thread owns a
// float4 x-column: same smem bytes per voxel, half the LDS/STS instructions
// and half the barrier cost per voxel. 4 separable exchange rounds per plane
// through 2 ping-pong float4 buffers; z handled by register rings.
__global__ __launch_bounds__(NTH, 2)
void soft_skel_kernel(const float* __restrict__ img, float* __restrict__ out) {
    __shared__ float4 sA[CH * CW];
    __shared__ float4 sB[CH * CW];

    const int tid = threadIdx.x;
    const int cx  = tid % CW;            // float4 column index
    const int iy  = tid / CW;            // row index (with halo)
    const int bx0 = blockIdx.x * TX;
    const int by0 = blockIdx.y * TY;
    const int bz  = blockIdx.z;
    const int b   = bz / ZCHUNKS;
    const int z0  = (bz % ZCHUNKS) * ZCK;
    const int z1  = z0 + ZCK;

    const int gx = bx0 + cx * 4 - 4;     // first element of the quad
    const int gy = by0 + iy - 2;

    // quad is always fully inside or fully outside the image in x
    const bool inImg = (gx >= 0) && (gx < X) && (gy >= 0) && (gy < Y);
    const bool outP  = (iy >= 2) && (iy <= CH - 3) && (cx >= 1) && (cx <= CW - 2);

    // loop-invariant shared offsets (clamped at edges; clamp garbage stays in
    // lanes/rows that interior outputs never consume)
    const int xl = (cx == 0)      ? 0      : cx - 1;
    const int xr = (cx == CW - 1) ? CW - 1 : cx + 1;
    const int yu = (iy == 0)      ? 0      : iy - 1;
    const int yd = (iy == CH - 1) ? CH - 1 : iy + 1;
    const int offC = iy * CW + cx;
    const int offL = iy * CW + xl;
    const int offR = iy * CW + xr;
    const int offU = yu * CW + cx;
    const int offD = yd * CW + cx;

    const float  PINF = __int_as_float(0x7f800000);
    const float  NINF = __int_as_float(0xff800000);
    const float4 PI4  = make_float4(PINF, PINF, PINF, PINF);

    const long base = (long)b * Z * YX + (long)gy * X + gx;
    const float* pIn = img + base + (long)(z0 - 1) * YX;   // next plane to load
    float*       pO  = out + base + (long)z0 * YX;

    // img ring: v0 = plane zi-2, v1 = zi-1, v2 = zi
    float4 v0 = PI4, v1 = PI4, v2;
    // erode ring: e0 = e(zi-3), e1 = e(zi-2)
    float4 e0 = make_float4(NINF, NINF, NINF, NINF), e1 = e0;

    // preload plane z0-2
    v2 = (inImg && (z0 - 2) >= 0) ? *(const float4*)(pIn - YX) : PI4;

    for (int zi = z0 - 2; zi <= z1 + 1; ++zi) {
        // ---- prefetch plane zi+1 (overlaps with this plane's compute)
        float4 vn = PI4;
        {
            const int zn = zi + 1;
            if (inImg && (unsigned)zn < (unsigned)Z)
                vn = *(const float4*)pIn;
            pIn += YX;
        }

        // ---- erode-z at plane zc = zi-1 (registers)
        float4 zm = fmin4(v0, fmin4(v1, v2));

        // ---- erode-y via smem (buffer A)
        sA[offC] = zm;
        __syncthreads();
        float4 yb = fmin4(sA[offU], fmin4(zm, sA[offD]));
        sB[offC] = yb;
        __syncthreads();

        // ---- erode-x (buffer B) + domain mask (-inf outside for dilate pad)
        {
            float4 L = sB[offL];
            float4 R = sB[offR];
            float4 ex;
            ex.x = min3(L.w,  yb.x, yb.y);
            ex.y = min3(yb.x, yb.y, yb.z);
            ex.z = min3(yb.y, yb.z, yb.w);
            ex.w = min3(yb.z, yb.w, R.x);
            const int  zc = zi - 1;
            const bool vC = inImg && ((unsigned)zc < (unsigned)Z);
            float4 en;
            en.x = vC ? ex.x : NINF;
            en.y = vC ? ex.y : NINF;
            en.z = vC ? ex.z : NINF;
            en.w = vC ? ex.w : NINF;

            // ---- dilate-z at plane zo = zi-2 (registers)
            float4 dd = fmax4(e0, fmax4(e1, en));
            e0 = e1; e1 = en;

            // ---- dilate-y via smem (buffer A reusable after sync above)
            sA[offC] = dd;
            __syncthreads();
            float4 m = fmax4(sA[offU], fmax4(dd, sA[offD]));
            sB[offC] = m;
            __syncthreads();

            // ---- dilate-x + output: opened at plane zo = zi-2
            if (zi >= z0 + 2) {
                if (outP) {
                    float4 Lm = sB[offL];
                    float4 Rm = sB[offR];
                    float4 r;
                    r.x = fmaxf(v0.x - max3(Lm.w, m.x, m.y), 0.0f);
                    r.y = fmaxf(v0.y - max3(m.x,  m.y, m.z), 0.0f);
                    r.z = fmaxf(v0.z - max3(m.y,  m.z, m.w), 0.0f);
                    r.w = fmaxf(v0.w - max3(m.z,  m.w, Rm.x), 0.0f);
                    *(float4*)pO = r;   // v0 = img at plane zo
                }
                pO += YX;
            }
        }

        // ---- shift img ring
        v0 = v1; v1 = v2; v2 = vn;
    }
}

extern "C" void kernel_launch(void* const* d_in, const int* in_sizes, int n_in,
                              void* d_out, int out_size) {
    (void)in_sizes; (void)n_in; (void)out_size;
    const float* img = (const float*)d_in[0];
    float* out = (float*)d_out;
    dim3 grid(X / TX, Y / TY, NB * ZCHUNKS);
    soft_skel_kernel<<<grid, NTH>>>(img, out);
}